// round 8
// baseline (speedup 1.0000x reference)
#include <cuda_runtime.h>
#include <cuda_fp16.h>

#define UU 256
#define SS 128
#define TT 128
#define BB 256
#define BC 2
#define TPB 1024
#define NQ 4
#define IH  (UU/NQ)   // 64 recurrent i per quarter
#define ISH (SS/NQ)   // 32 sensory i per quarter

// Packed 8-byte parameter element: {half2 (a,b), fp32 we}
//   a = 0.5*sigma, b = -0.5*sigma*mu  (tanh-form argument coeffs)
//   we = softplus(w) * erev
struct __align__(8) P8 { __half2 ab; float we; };

__device__ P8    g_rp[UU*UU];
__device__ P8    g_sp[SS*UU];
__device__ float g_cmt[UU];
__device__ float g_gl[UU];
__device__ float g_glvl[UU];

__device__ __forceinline__ __half2 htanh2(__half2 x){
    unsigned xi = *reinterpret_cast<unsigned*>(&x), yi;
    asm("tanh.approx.f16x2 %0, %1;" : "=r"(yi) : "r"(xi));
    return *reinterpret_cast<__half2*>(&yi);
}
__device__ __forceinline__ float tanhfast(float x){ float y; asm("tanh.approx.f32 %0, %1;" : "=f"(y) : "f"(x)); return y; }
__device__ __forceinline__ float rcpf(float x){ float y; asm("rcp.approx.ftz.f32 %0, %1;" : "=f"(y) : "f"(x)); return y; }
__device__ __forceinline__ float softplusf(float x){ return log1pf(expf(x)); }

__global__ void prep_kernel(const float* __restrict__ sw,  const float* __restrict__ smu,
                            const float* __restrict__ ssig,const float* __restrict__ serev,
                            const float* __restrict__ w,   const float* __restrict__ mu,
                            const float* __restrict__ sig, const float* __restrict__ erev,
                            const float* __restrict__ gleak, const float* __restrict__ vleak,
                            const float* __restrict__ cm, float* __restrict__ ponder_slot)
{
    int idx = blockIdx.x * blockDim.x + threadIdx.x;
    if (idx < UU*UU) {
        float s = sig[idx];
        g_rp[idx].ab = __floats2half2_rn(0.5f*s, -0.5f*s*mu[idx]);
        g_rp[idx].we = softplusf(w[idx]) * erev[idx];
    }
    if (idx < SS*UU) {
        float s = ssig[idx];
        g_sp[idx].ab = __floats2half2_rn(0.5f*s, -0.5f*s*smu[idx]);
        g_sp[idx].we = softplusf(sw[idx]) * serev[idx];
    }
    if (idx < UU) {
        float g = softplusf(gleak[idx]);
        g_gl[idx]   = g;
        g_glvl[idx] = g * vleak[idx];
        g_cmt[idx]  = softplusf(cm[idx]) * 6.0f;   // softplus(cm) / (1/ODE_UNFOLDS)
    }
    if (idx == 0) *ponder_slot = 0.0f;
}

template<int N> struct IC { static constexpr int value = N; };

__global__ __launch_bounds__(TPB, 1) void actltc_main(
    const float* __restrict__ x,
    const float* __restrict__ input_w,  const float* __restrict__ input_b,
    const float* __restrict__ output_w, const float* __restrict__ output_b,
    const float* __restrict__ halt_w,   const float* __restrict__ halt_b,
    float* __restrict__ out)
{
    __shared__ __half2 vh[UU];          // packed (v_b0, v_b1) — tanh-arg copy of state
    __shared__ __half2 xh[SS];          // packed (xin_b0, xin_b1)
    __shared__ float pn[NQ][BC][UU];    // partial sum(we*tanh) per quarter
    __shared__ float pd[NQ][BC][UU];    // partial sum(|we|*tanh) per quarter
    __shared__ float red[BC][UU/32];
    __shared__ float logit_s[BC];

    const int tid = threadIdx.x;
    const int j   = tid & (UU-1);        // post-synaptic unit (column)
    const int q   = tid >> 8;            // i-range quarter
    const int b0  = blockIdx.x * BC;     // first batch element of this CTA

    const float2* __restrict__ rp2 = (const float2*)g_rp;
    const float2* __restrict__ sp2 = (const float2*)g_sp;

    // Per-thread input-mapping coeffs (threads tid<SS handle the xin load)
    const float iw = (tid < SS) ? input_w[tid] : 0.f;
    const float ib = (tid < SS) ? input_b[tid] : 0.f;

    // ---- Preamble: fold tanh-identity constants (0.5*sum of weights) per j.
    {
        float cn = 0.f, cd = 0.f;
        const P8* __restrict__ pr = g_rp + j + (unsigned)(q * IH) * UU;
        #pragma unroll 8
        for (int i = 0; i < IH; i++) {
            float v = pr[(unsigned)i * UU].we;
            cn += v; cd += fabsf(v);
        }
        float scn = 0.f, scd = 0.f;
        const P8* __restrict__ ps = g_sp + j + (unsigned)(q * ISH) * UU;
        #pragma unroll 8
        for (int i = 0; i < ISH; i++) {
            float v = ps[(unsigned)i * UU].we;
            scn += v; scd += fabsf(v);
        }
        pn[q][0][j] = cn;  pd[q][0][j] = cd;
        pn[q][1][j] = scn; pd[q][1][j] = scd;
    }
    __syncthreads();
    const float cmt = g_cmt[j];
    const float gnc = g_glvl[j] + 0.5f * ((pn[0][0][j]+pn[1][0][j]) + (pn[2][0][j]+pn[3][0][j]));
    const float k2  = cmt + g_gl[j] + 1e-8f
                    + 0.5f * ((pd[0][0][j]+pd[1][0][j]) + (pd[2][0][j]+pd[3][0][j]));
    const float scn0 = 0.5f * ((pn[0][1][j]+pn[1][1][j]) + (pn[2][1][j]+pn[3][1][j]));
    const float scd0 = 0.5f * ((pd[0][1][j]+pd[1][1][j]) + (pd[2][1][j]+pd[3][1][j]));
    const float hw  = halt_w[j];
    const float hb  = halt_b[0];
    __syncthreads();

    float v_reg[BC], acc[BC], sn[BC], sd[BC], halt_sum[BC];
    bool  still[BC];
    #pragma unroll
    for (int k = 0; k < BC; k++) { v_reg[k] = 0.f; acc[k] = 0.f; }
    if (q == 0) vh[j] = __floats2half2_rn(0.f, 0.f);
    float ponder = 0.f;
    __syncthreads();

    // One ODE unfold for the batch subset given by compile-time mask M.
    // Both batch lanes ride one tanh.approx.f16x2; accumulation stays fp32.
    auto unfold = [&](auto MC) {
        constexpr int M = MC.value;
        float num0 = 0.f, den0 = 0.f, num1 = 0.f, den1 = 0.f;
        const float2*  __restrict__ pr = rp2 + j + (unsigned)(q * IH) * UU;
        const __half2* __restrict__ vv = vh + q * IH;
        #pragma unroll 4
        for (int i = 0; i < IH; i++) {
            float2 raw = pr[(unsigned)i * UU];                  // one LDG.64
            __half2 ab = *reinterpret_cast<const __half2*>(&raw.x);
            float  wev = raw.y;
            float  aw  = fabsf(wev);
            __half2 arg = __hfma2(__half2half2(__low2half(ab)), vv[i],
                                  __half2half2(__high2half(ab)));
            __half2 th2 = htanh2(arg);                          // 1 MUFU, both lanes
            if constexpr (M & 1) {
                float th = __low2float(th2);
                num0 = fmaf(wev, th, num0);
                den0 = fmaf(aw,  th, den0);
            }
            if constexpr (M & 2) {
                float th = __high2float(th2);
                num1 = fmaf(wev, th, num1);
                den1 = fmaf(aw,  th, den1);
            }
        }
        if constexpr (M & 1) { pn[q][0][j] = num0; pd[q][0][j] = den0; }
        if constexpr (M & 2) { pn[q][1][j] = num1; pd[q][1][j] = den1; }
        __syncthreads();
        if constexpr (M & 1) {
            float nm = (pn[0][0][j] + pn[1][0][j]) + (pn[2][0][j] + pn[3][0][j]);
            float dn = (pd[0][0][j] + pd[1][0][j]) + (pd[2][0][j] + pd[3][0][j]);
            nm = fmaf(0.5f, nm, sn[0]);
            dn = fmaf(0.5f, dn, sd[0]);
            v_reg[0] = (fmaf(cmt, v_reg[0], gnc) + nm) * rcpf(k2 + dn);
        }
        if constexpr (M & 2) {
            float nm = (pn[0][1][j] + pn[1][1][j]) + (pn[2][1][j] + pn[3][1][j]);
            float dn = (pd[0][1][j] + pd[1][1][j]) + (pd[2][1][j] + pd[3][1][j]);
            nm = fmaf(0.5f, nm, sn[1]);
            dn = fmaf(0.5f, dn, sd[1]);
            v_reg[1] = (fmaf(cmt, v_reg[1], gnc) + nm) * rcpf(k2 + dn);
        }
        if (q == 0) vh[j] = __floats2half2_rn(v_reg[0], v_reg[1]);  // both lanes always valid
        __syncthreads();
    };

    for (int t = 0; t < TT; t++) {
        // Affine input mapping, packed into xh (threads 0..127)
        if (tid < SS) {
            float x0v = fmaf(x[((size_t)b0       * TT + t) * SS + tid], iw, ib);
            float x1v = fmaf(x[((size_t)(b0 + 1) * TT + t) * SS + tid], iw, ib);
            xh[tid] = __floats2half2_rn(x0v, x1v);
        }
        __syncthreads();

        // Sensory sums (hoisted: depend only on xin, not v), i-split 4-way
        {
            float s0n = 0.f, s0d = 0.f, s1n = 0.f, s1d = 0.f;
            const float2*  __restrict__ ps = sp2 + j + (unsigned)(q * ISH) * UU;
            const __half2* __restrict__ xx = xh + q * ISH;
            #pragma unroll 4
            for (int i = 0; i < ISH; i++) {
                float2 raw = ps[(unsigned)i * UU];
                __half2 ab = *reinterpret_cast<const __half2*>(&raw.x);
                float  wev = raw.y;
                float  aw  = fabsf(wev);
                __half2 arg = __hfma2(__half2half2(__low2half(ab)), xx[i],
                                      __half2half2(__high2half(ab)));
                __half2 th2 = htanh2(arg);
                float t0 = __low2float(th2), t1 = __high2float(th2);
                s0n = fmaf(wev, t0, s0n);  s0d = fmaf(aw, t0, s0d);
                s1n = fmaf(wev, t1, s1n);  s1d = fmaf(aw, t1, s1d);
            }
            pn[q][0][j] = s0n; pd[q][0][j] = s0d;
            pn[q][1][j] = s1n; pd[q][1][j] = s1d;
            __syncthreads();
            sn[0] = fmaf(0.5f, (pn[0][0][j]+pn[1][0][j]) + (pn[2][0][j]+pn[3][0][j]), scn0);
            sd[0] = fmaf(0.5f, (pd[0][0][j]+pd[1][0][j]) + (pd[2][0][j]+pd[3][0][j]), scd0);
            sn[1] = fmaf(0.5f, (pn[0][1][j]+pn[1][1][j]) + (pn[2][1][j]+pn[3][1][j]), scn0);
            sd[1] = fmaf(0.5f, (pd[0][1][j]+pd[1][1][j]) + (pd[2][1][j]+pd[3][1][j]), scd0);
            __syncthreads();   // protect pn/pd before unfold overwrites them
        }

        #pragma unroll
        for (int k = 0; k < BC; k++) { acc[k] = 0.f; halt_sum[k] = 0.f; still[k] = true; }

        // ACT loop — skip fully-dead iterations (weight would be 0)
        for (int n = 0; n < 10; n++) {
            int mask = (still[0] ? 1 : 0) | (still[1] ? 2 : 0);
            if (mask == 0) break;
            for (int f = 0; f < 6; f++) {
                if (mask == 3)      unfold(IC<3>{});
                else if (mask == 1) unfold(IC<1>{});
                else                unfold(IC<2>{});
            }
            // Halting logit: reduce v . halt_w over 256 units (q==0 warps only)
            if (q == 0) {
                float c0 = v_reg[0] * hw, c1 = v_reg[1] * hw;
                #pragma unroll
                for (int o = 16; o > 0; o >>= 1) {
                    c0 += __shfl_down_sync(0xffffffffu, c0, o);
                    c1 += __shfl_down_sync(0xffffffffu, c1, o);
                }
                if ((j & 31) == 0) { red[0][j >> 5] = c0; red[1][j >> 5] = c1; }
            }
            __syncthreads();
            if (tid < BC) {
                float s = red[tid][0];
                #pragma unroll
                for (int w = 1; w < UU/32; w++) s += red[tid][w];
                logit_s[tid] = s + hb;
            }
            __syncthreads();
            // ACT bookkeeping (redundant in all threads; identical values)
            #pragma unroll
            for (int k = 0; k < BC; k++) if (still[k]) {
                float p       = fmaf(0.5f, tanhfast(0.5f * logit_s[k]), 0.5f);  // sigmoid
                float new_sum = halt_sum[k] + p;
                bool  halting = (n == 9) || (new_sum >= 0.99f);
                float r       = 1.f - halt_sum[k];
                float wgt     = halting ? r : p;
                acc[k]        = fmaf(wgt, v_reg[k], acc[k]);
                ponder       += 1.f + (halting ? r : 0.f);   // n_updates + remainders
                halt_sum[k]   = new_sum;
                still[k]      = !halting;
            }
        }

        // Per-timestep outputs; new state = acc
        #pragma unroll
        for (int k = 0; k < BC; k++) {
            if (q == 0)
                out[((size_t)(b0 + k) * TT + t) * UU + j] = fmaf(acc[k], output_w[j], output_b[j]);
            v_reg[k] = acc[k];
        }
        if (q == 0) vh[j] = __floats2half2_rn(acc[0], acc[1]);  // next-t unfold reads this
    }

    // Final hidden state
    if (q == 0) {
        #pragma unroll
        for (int k = 0; k < BC; k++)
            out[(size_t)BB * TT * UU + (size_t)(b0 + k) * UU + j] = acc[k];
    }

    // Ponder: sum over (b,t) of (n_updates + remainders), then mean over batch
    if (tid == 0)
        atomicAdd(out + (size_t)BB * TT * UU + (size_t)BB * UU, ponder * (1.0f / (float)BB));
}

extern "C" void kernel_launch(void* const* d_in, const int* in_sizes, int n_in,
                              void* d_out, int out_size)
{
    const float* x            = (const float*)d_in[0];
    const float* input_w      = (const float*)d_in[1];
    const float* input_b      = (const float*)d_in[2];
    const float* sensory_w    = (const float*)d_in[3];
    const float* sensory_mu   = (const float*)d_in[4];
    const float* sensory_sig  = (const float*)d_in[5];
    const float* sensory_erev = (const float*)d_in[6];
    const float* w            = (const float*)d_in[7];
    const float* mu           = (const float*)d_in[8];
    const float* sigma        = (const float*)d_in[9];
    const float* erev         = (const float*)d_in[10];
    const float* gleak        = (const float*)d_in[11];
    const float* vleak        = (const float*)d_in[12];
    const float* cm           = (const float*)d_in[13];
    const float* output_w     = (const float*)d_in[14];
    const float* output_b     = (const float*)d_in[15];
    const float* halt_w       = (const float*)d_in[16];
    const float* halt_b       = (const float*)d_in[17];
    float* out = (float*)d_out;

    float* ponder_slot = out + (size_t)BB * TT * UU + (size_t)BB * UU;

    prep_kernel<<<(UU*UU + 255) / 256, 256>>>(
        sensory_w, sensory_mu, sensory_sig, sensory_erev,
        w, mu, sigma, erev, gleak, vleak, cm, ponder_slot);

    actltc_main<<<BB / BC, TPB>>>(
        x, input_w, input_b, output_w, output_b, halt_w, halt_b, out);
}